// round 2
// baseline (speedup 1.0000x reference)
#include <cuda_runtime.h>
#include <cstddef>

#define BATCH 16
#define NVERT 250000
#define NFACE 500000
#define NADJ  (6 * NFACE)   // 3,000,000 adjacency entries

// ---------------------------------------------------------------------------
// Device scratch (static; no runtime allocation allowed)
// ---------------------------------------------------------------------------
__device__ int    g_deg[NVERT];                     // per-vertex entry count
__device__ int    g_start[NVERT];                   // CSR offsets (exclusive scan)
__device__ int    g_cursor[NVERT];                  // fill cursors
__device__ int    g_adj[NADJ];                      // neighbor indices
__device__ float4 g_vert4[(size_t)NVERT * BATCH];   // [v][b] batch-contiguous, 64 MB

// ---------------------------------------------------------------------------
// 1. Zero degrees
// ---------------------------------------------------------------------------
__global__ void zero_deg_kernel() {
    int i = blockIdx.x * blockDim.x + threadIdx.x;
    if (i < NVERT) g_deg[i] = 0;
}

// ---------------------------------------------------------------------------
// 2. Count degrees: each face gives 2 entries per endpoint
// ---------------------------------------------------------------------------
__global__ void count_deg_kernel(const int* __restrict__ faces) {
    int f = blockIdx.x * blockDim.x + threadIdx.x;
    if (f >= NFACE) return;
    int a = faces[3 * f + 0];
    int b = faces[3 * f + 1];
    int c = faces[3 * f + 2];
    atomicAdd(&g_deg[a], 2);
    atomicAdd(&g_deg[b], 2);
    atomicAdd(&g_deg[c], 2);
}

// ---------------------------------------------------------------------------
// 3. Exclusive scan of degrees (single block, 1024 threads, chunked)
// ---------------------------------------------------------------------------
__global__ void scan_kernel() {
    __shared__ int ssum[1024];
    int t = threadIdx.x;
    const int chunk = (NVERT + 1023) / 1024;  // 245
    int begin = t * chunk;
    int end = begin + chunk;
    if (end > NVERT) end = NVERT;
    if (begin > NVERT) begin = NVERT;

    int s = 0;
    for (int i = begin; i < end; ++i) s += g_deg[i];
    ssum[t] = s;
    __syncthreads();

    // Hillis-Steele inclusive scan over 1024 partials
    for (int d = 1; d < 1024; d <<= 1) {
        int add = (t >= d) ? ssum[t - d] : 0;
        __syncthreads();
        ssum[t] += add;
        __syncthreads();
    }

    int off = (t == 0) ? 0 : ssum[t - 1];
    for (int i = begin; i < end; ++i) {
        int d = g_deg[i];
        g_start[i] = off;
        g_cursor[i] = off;
        off += d;
    }
}

// ---------------------------------------------------------------------------
// 4. Fill adjacency lists (order within a list is irrelevant: we only sum)
// ---------------------------------------------------------------------------
__global__ void fill_adj_kernel(const int* __restrict__ faces) {
    int f = blockIdx.x * blockDim.x + threadIdx.x;
    if (f >= NFACE) return;
    int a = faces[3 * f + 0];
    int b = faces[3 * f + 1];
    int c = faces[3 * f + 2];

    int pa = atomicAdd(&g_cursor[a], 2);
    g_adj[pa] = b;  g_adj[pa + 1] = c;
    int pb = atomicAdd(&g_cursor[b], 2);
    g_adj[pb] = a;  g_adj[pb + 1] = c;
    int pc = atomicAdd(&g_cursor[c], 2);
    g_adj[pc] = a;  g_adj[pc + 1] = b;
}

// ---------------------------------------------------------------------------
// 5. Transpose vert [B][N][3] -> g_vert4 [N][B] (float4, batch-contiguous)
//    One neighbor lookup then reads 256 contiguous bytes (8 full sectors).
// ---------------------------------------------------------------------------
__global__ void transpose_kernel(const float* __restrict__ vert) {
    size_t tid = (size_t)blockIdx.x * blockDim.x + threadIdx.x;
    if (tid >= (size_t)NVERT * BATCH) return;
    int v = (int)(tid >> 4);
    int b = (int)(tid & 15);
    const float* p = vert + ((size_t)b * NVERT + (size_t)v) * 3;
    g_vert4[tid] = make_float4(p[0], p[1], p[2], 0.0f);
}

// ---------------------------------------------------------------------------
// 6. Gather + finalize. 2 threads per vertex: each handles 8 batches.
//    Paired lanes (same v) share adjacency reads (L1 broadcast) and together
//    consume a neighbor's full 256B batch row.
// ---------------------------------------------------------------------------
__global__ void __launch_bounds__(256)
gather_kernel(float* __restrict__ out) {
    int tid = blockIdx.x * blockDim.x + threadIdx.x;
    if (tid >= NVERT * 2) return;
    int v = tid >> 1;
    int half = tid & 1;          // batches [half*8, half*8+8)
    int bbase = half * 8;

    int s = g_start[v];
    int d = g_deg[v];

    float ax[8], ay[8], az[8];
#pragma unroll
    for (int b = 0; b < 8; ++b) { ax[b] = 0.f; ay[b] = 0.f; az[b] = 0.f; }

    const int* __restrict__ adj = g_adj + s;
    for (int k = 0; k < d; ++k) {
        int u = __ldg(&adj[k]);
        const float4* __restrict__ pu = &g_vert4[(size_t)u * BATCH + bbase];
#pragma unroll
        for (int b = 0; b < 8; ++b) {
            float4 p = __ldg(&pu[b]);
            ax[b] += p.x;
            ay[b] += p.y;
            az[b] += p.z;
        }
    }

    float inv = 1.0f / fmaxf((float)d, 1.0f);
    const float4* __restrict__ pv = &g_vert4[(size_t)v * BATCH + bbase];
#pragma unroll
    for (int b = 0; b < 8; ++b) {
        float4 p = pv[b];
        float lx = ax[b] * inv - p.x;
        float ly = ay[b] * inv - p.y;
        float lz = az[b] * inv - p.z;
        out[(size_t)(bbase + b) * NVERT + v] = sqrtf(lx * lx + ly * ly + lz * lz);
    }
}

// ---------------------------------------------------------------------------
extern "C" void kernel_launch(void* const* d_in, const int* in_sizes, int n_in,
                              void* d_out, int out_size) {
    const float* vert = (const float*)d_in[0];
    const int* faces = (const int*)d_in[1];
    float* out = (float*)d_out;

    const int T = 256;

    zero_deg_kernel<<<(NVERT + T - 1) / T, T>>>();
    count_deg_kernel<<<(NFACE + T - 1) / T, T>>>(faces);
    scan_kernel<<<1, 1024>>>();
    fill_adj_kernel<<<(NFACE + T - 1) / T, T>>>(faces);

    {
        size_t total = (size_t)NVERT * BATCH;
        transpose_kernel<<<(int)((total + T - 1) / T), T>>>(vert);
    }

    gather_kernel<<<(NVERT * 2 + T - 1) / T, T>>>(out);
}

// round 3
// speedup vs baseline: 1.2538x; 1.2538x over previous
#include <cuda_runtime.h>
#include <cstddef>

#define BATCH 16
#define NVERT 250000
#define NFACE 500000
#define NADJ  (6 * NFACE)   // 3,000,000 adjacency entries

// ---------------------------------------------------------------------------
// Device scratch (static; no runtime allocation allowed)
// ---------------------------------------------------------------------------
__device__ int    g_deg[NVERT];                     // per-vertex entry count
__device__ int    g_start[NVERT];                   // CSR offsets (exclusive scan)
__device__ int    g_cursor[NVERT];                  // fill cursors
__device__ int    g_adj[NADJ];                      // neighbor indices
__device__ float4 g_vert4[(size_t)NVERT * BATCH];   // [v][b] batch-contiguous, 64 MB

// ---------------------------------------------------------------------------
// 1. Zero degrees
// ---------------------------------------------------------------------------
__global__ void zero_deg_kernel() {
    int i = blockIdx.x * blockDim.x + threadIdx.x;
    if (i < NVERT) g_deg[i] = 0;
}

// ---------------------------------------------------------------------------
// 2. Count degrees: each face gives 2 entries per endpoint
// ---------------------------------------------------------------------------
__global__ void count_deg_kernel(const int* __restrict__ faces) {
    int f = blockIdx.x * blockDim.x + threadIdx.x;
    if (f >= NFACE) return;
    int a = faces[3 * f + 0];
    int b = faces[3 * f + 1];
    int c = faces[3 * f + 2];
    atomicAdd(&g_deg[a], 2);
    atomicAdd(&g_deg[b], 2);
    atomicAdd(&g_deg[c], 2);
}

// ---------------------------------------------------------------------------
// 3. Exclusive scan of degrees (single block, 1024 threads, chunked)
// ---------------------------------------------------------------------------
__global__ void scan_kernel() {
    __shared__ int ssum[1024];
    int t = threadIdx.x;
    const int chunk = (NVERT + 1023) / 1024;  // 245
    int begin = t * chunk;
    int end = begin + chunk;
    if (end > NVERT) end = NVERT;
    if (begin > NVERT) begin = NVERT;

    int s = 0;
    for (int i = begin; i < end; ++i) s += g_deg[i];
    ssum[t] = s;
    __syncthreads();

    // Hillis-Steele inclusive scan over 1024 partials
    for (int d = 1; d < 1024; d <<= 1) {
        int add = (t >= d) ? ssum[t - d] : 0;
        __syncthreads();
        ssum[t] += add;
        __syncthreads();
    }

    int off = (t == 0) ? 0 : ssum[t - 1];
    for (int i = begin; i < end; ++i) {
        int d = g_deg[i];
        g_start[i] = off;
        g_cursor[i] = off;
        off += d;
    }
}

// ---------------------------------------------------------------------------
// 4. Fill adjacency lists (order within a list is irrelevant: we only sum)
// ---------------------------------------------------------------------------
__global__ void fill_adj_kernel(const int* __restrict__ faces) {
    int f = blockIdx.x * blockDim.x + threadIdx.x;
    if (f >= NFACE) return;
    int a = faces[3 * f + 0];
    int b = faces[3 * f + 1];
    int c = faces[3 * f + 2];

    int pa = atomicAdd(&g_cursor[a], 2);
    g_adj[pa] = b;  g_adj[pa + 1] = c;
    int pb = atomicAdd(&g_cursor[b], 2);
    g_adj[pb] = a;  g_adj[pb + 1] = c;
    int pc = atomicAdd(&g_cursor[c], 2);
    g_adj[pc] = a;  g_adj[pc + 1] = b;
}

// ---------------------------------------------------------------------------
// 5. Transpose vert [B][N][3] -> g_vert4 [N][B] (float4, batch-contiguous)
//    Writes fully coalesced; scattered reads get sector reuse via L2.
// ---------------------------------------------------------------------------
__global__ void transpose_kernel(const float* __restrict__ vert) {
    size_t tid = (size_t)blockIdx.x * blockDim.x + threadIdx.x;
    if (tid >= (size_t)NVERT * BATCH) return;
    int v = (int)(tid >> 4);
    int b = (int)(tid & 15);
    const float* p = vert + ((size_t)b * NVERT + (size_t)v) * 3;
    g_vert4[tid] = make_float4(p[0], p[1], p[2], 0.0f);
}

// ---------------------------------------------------------------------------
// 6. Gather + finalize: ONE WARP PER VERTEX.
//    lane l: batch b = l&15, parity j = l>>4.
//    Half-warp reads one neighbor's full 256B batch row per iteration
//    => 4 cache lines per LDG.128 instruction instead of 32.
// ---------------------------------------------------------------------------
__global__ void __launch_bounds__(256)
gather_kernel(float* __restrict__ out) {
    int w = (blockIdx.x * blockDim.x + threadIdx.x) >> 5;  // global warp = vertex
    if (w >= NVERT) return;
    int v = w;
    int lane = threadIdx.x & 31;
    int b = lane & 15;
    int j = lane >> 4;   // 0: even entries, 1: odd entries

    int s = g_start[v];
    int d = g_deg[v];

    float ax = 0.f, ay = 0.f, az = 0.f;

    const int* __restrict__ adj = g_adj + s;

    int k = j;
    int u = (k < d) ? __ldg(&adj[k]) : 0;
    while (k < d) {
        int k2 = k + 2;
        int u_next = (k2 < d) ? __ldg(&adj[k2]) : 0;   // prefetch: breaks chain
        float4 p = __ldg(&g_vert4[(size_t)u * BATCH + b]);
        ax += p.x;
        ay += p.y;
        az += p.z;
        u = u_next;
        k = k2;
    }

    // Combine the two parity halves (lane l <-> lane l^16 hold same batch b)
    ax += __shfl_xor_sync(0xffffffffu, ax, 16);
    ay += __shfl_xor_sync(0xffffffffu, ay, 16);
    az += __shfl_xor_sync(0xffffffffu, az, 16);

    if (j == 0) {
        float inv = 1.0f / fmaxf((float)d, 1.0f);
        float4 p = __ldg(&g_vert4[(size_t)v * BATCH + b]);
        float lx = ax * inv - p.x;
        float ly = ay * inv - p.y;
        float lz = az * inv - p.z;
        out[(size_t)b * NVERT + v] = sqrtf(lx * lx + ly * ly + lz * lz);
    }
}

// ---------------------------------------------------------------------------
extern "C" void kernel_launch(void* const* d_in, const int* in_sizes, int n_in,
                              void* d_out, int out_size) {
    const float* vert = (const float*)d_in[0];
    const int* faces = (const int*)d_in[1];
    float* out = (float*)d_out;

    const int T = 256;

    zero_deg_kernel<<<(NVERT + T - 1) / T, T>>>();
    count_deg_kernel<<<(NFACE + T - 1) / T, T>>>(faces);
    scan_kernel<<<1, 1024>>>();
    fill_adj_kernel<<<(NFACE + T - 1) / T, T>>>(faces);

    {
        size_t total = (size_t)NVERT * BATCH;
        transpose_kernel<<<(int)((total + T - 1) / T), T>>>(vert);
    }

    // one warp per vertex: 8 vertices per 256-thread block
    {
        int warps_per_block = T / 32;                       // 8
        int blocks = (NVERT + warps_per_block - 1) / warps_per_block;  // 31250
        gather_kernel<<<blocks, T>>>(out);
    }
}

// round 4
// speedup vs baseline: 3.8670x; 3.0842x over previous
#include <cuda_runtime.h>
#include <cstddef>

#define BATCH 16
#define NVERT 250000
#define NFACE 500000
#define NADJ  (6 * NFACE)          // 3,000,000 adjacency entries
#define SCAN_B 1024
#define NBLK ((NVERT + SCAN_B - 1) / SCAN_B)   // 245

// ---------------------------------------------------------------------------
// Device scratch (static; no runtime allocation allowed)
// ---------------------------------------------------------------------------
__device__ int    g_deg[NVERT];
__device__ int    g_start[NVERT];
__device__ int    g_cursor[NVERT];
__device__ int    g_adj[NADJ];
__device__ int    g_blocksum[NBLK];
__device__ int    g_blockoff[NBLK];
__device__ float4 g_vert4[(size_t)NVERT * BATCH];   // [v][b] batch-contiguous, 64 MB

// ---------------------------------------------------------------------------
// 1. Zero degrees
// ---------------------------------------------------------------------------
__global__ void zero_deg_kernel() {
    int i = blockIdx.x * blockDim.x + threadIdx.x;
    if (i < NVERT) g_deg[i] = 0;
}

// ---------------------------------------------------------------------------
// 2. Count degrees
// ---------------------------------------------------------------------------
__global__ void count_deg_kernel(const int* __restrict__ faces) {
    int f = blockIdx.x * blockDim.x + threadIdx.x;
    if (f >= NFACE) return;
    int a = faces[3 * f + 0];
    int b = faces[3 * f + 1];
    int c = faces[3 * f + 2];
    atomicAdd(&g_deg[a], 2);
    atomicAdd(&g_deg[b], 2);
    atomicAdd(&g_deg[c], 2);
}

// ---------------------------------------------------------------------------
// 3a. Per-block reduce of degrees (coalesced)
// ---------------------------------------------------------------------------
__global__ void scan_reduce_kernel() {
    __shared__ int sdata[SCAN_B / 32];
    int i = blockIdx.x * SCAN_B + threadIdx.x;
    int v = (i < NVERT) ? g_deg[i] : 0;
    // warp reduce
    for (int o = 16; o > 0; o >>= 1) v += __shfl_down_sync(0xffffffffu, v, o);
    if ((threadIdx.x & 31) == 0) sdata[threadIdx.x >> 5] = v;
    __syncthreads();
    if (threadIdx.x < 32) {
        int w = (threadIdx.x < SCAN_B / 32) ? sdata[threadIdx.x] : 0;
        for (int o = 16; o > 0; o >>= 1) w += __shfl_down_sync(0xffffffffu, w, o);
        if (threadIdx.x == 0) g_blocksum[blockIdx.x] = w;
    }
}

// ---------------------------------------------------------------------------
// 3b. Exclusive scan of block sums (tiny; one block)
// ---------------------------------------------------------------------------
__global__ void scan_spine_kernel() {
    __shared__ int s[NBLK];
    int t = threadIdx.x;
    if (t < NBLK) s[t] = g_blocksum[t];
    __syncthreads();
    if (t == 0) {
        int run = 0;
        for (int i = 0; i < NBLK; ++i) {
            int v = s[i];
            s[i] = run;
            run += v;
        }
    }
    __syncthreads();
    if (t < NBLK) g_blockoff[t] = s[t];
}

// ---------------------------------------------------------------------------
// 3c. In-block exclusive scan + global offset (coalesced)
// ---------------------------------------------------------------------------
__global__ void scan_final_kernel() {
    __shared__ int s[SCAN_B];
    int t = threadIdx.x;
    int i = blockIdx.x * SCAN_B + t;
    int v = (i < NVERT) ? g_deg[i] : 0;
    s[t] = v;
    __syncthreads();
    // Hillis-Steele inclusive scan
    for (int d = 1; d < SCAN_B; d <<= 1) {
        int add = (t >= d) ? s[t - d] : 0;
        __syncthreads();
        s[t] += add;
        __syncthreads();
    }
    if (i < NVERT) {
        int excl = s[t] - v + g_blockoff[blockIdx.x];
        g_start[i] = excl;
        g_cursor[i] = excl;
    }
}

// ---------------------------------------------------------------------------
// 4. Fill adjacency lists
// ---------------------------------------------------------------------------
__global__ void fill_adj_kernel(const int* __restrict__ faces) {
    int f = blockIdx.x * blockDim.x + threadIdx.x;
    if (f >= NFACE) return;
    int a = faces[3 * f + 0];
    int b = faces[3 * f + 1];
    int c = faces[3 * f + 2];

    int pa = atomicAdd(&g_cursor[a], 2);
    g_adj[pa] = b;  g_adj[pa + 1] = c;
    int pb = atomicAdd(&g_cursor[b], 2);
    g_adj[pb] = a;  g_adj[pb + 1] = c;
    int pc = atomicAdd(&g_cursor[c], 2);
    g_adj[pc] = a;  g_adj[pc + 1] = b;
}

// ---------------------------------------------------------------------------
// 5. SMEM-tiled transpose: vert [B][N][3] -> g_vert4 [N][B]
//    Block handles 32 vertices. Reads: 16 coalesced 384B rows.
//    Writes: 8 KB contiguous float4 block, fully coalesced.
// ---------------------------------------------------------------------------
#define TVERTS 32
__global__ void __launch_bounds__(256)
transpose_kernel(const float* __restrict__ vert) {
    __shared__ float sm[BATCH][TVERTS * 3];   // 16 x 96 floats = 6 KB
    int v0 = blockIdx.x * TVERTS;
    int nv = NVERT - v0;
    if (nv > TVERTS) nv = TVERTS;
    int nfl = nv * 3;                          // floats per batch row

    // Load: 16 rows of nfl contiguous floats
    for (int i = threadIdx.x; i < BATCH * TVERTS * 3; i += 256) {
        int b = i / (TVERTS * 3);
        int r = i % (TVERTS * 3);
        if (r < nfl) {
            sm[b][r] = vert[((size_t)b * NVERT + v0) * 3 + r];
        }
    }
    __syncthreads();

    // Write: (vv, b) -> g_vert4[(v0+vv)*16 + b]
    for (int i = threadIdx.x; i < TVERTS * BATCH; i += 256) {
        int vv = i >> 4;
        int b = i & 15;
        if (vv < nv) {
            g_vert4[(size_t)(v0 + vv) * BATCH + b] =
                make_float4(sm[b][3 * vv], sm[b][3 * vv + 1], sm[b][3 * vv + 2], 0.0f);
        }
    }
}

// ---------------------------------------------------------------------------
// 6. Gather + finalize: one warp per vertex.
//    lane l: batch b = l&15, parity j = l>>4; half-warp per neighbor row.
// ---------------------------------------------------------------------------
__global__ void __launch_bounds__(256)
gather_kernel(float* __restrict__ out) {
    int w = (blockIdx.x * blockDim.x + threadIdx.x) >> 5;
    if (w >= NVERT) return;
    int v = w;
    int lane = threadIdx.x & 31;
    int b = lane & 15;
    int j = lane >> 4;

    int s = g_start[v];
    int d = g_deg[v];

    float ax = 0.f, ay = 0.f, az = 0.f;
    const int* __restrict__ adj = g_adj + s;

    int k = j;
    int u = (k < d) ? __ldg(&adj[k]) : 0;
    while (k < d) {
        int k2 = k + 2;
        int u_next = (k2 < d) ? __ldg(&adj[k2]) : 0;
        float4 p = __ldg(&g_vert4[(size_t)u * BATCH + b]);
        ax += p.x;
        ay += p.y;
        az += p.z;
        u = u_next;
        k = k2;
    }

    ax += __shfl_xor_sync(0xffffffffu, ax, 16);
    ay += __shfl_xor_sync(0xffffffffu, ay, 16);
    az += __shfl_xor_sync(0xffffffffu, az, 16);

    if (j == 0) {
        float inv = 1.0f / fmaxf((float)d, 1.0f);
        float4 p = __ldg(&g_vert4[(size_t)v * BATCH + b]);
        float lx = ax * inv - p.x;
        float ly = ay * inv - p.y;
        float lz = az * inv - p.z;
        out[(size_t)b * NVERT + v] = sqrtf(lx * lx + ly * ly + lz * lz);
    }
}

// ---------------------------------------------------------------------------
extern "C" void kernel_launch(void* const* d_in, const int* in_sizes, int n_in,
                              void* d_out, int out_size) {
    const float* vert = (const float*)d_in[0];
    const int* faces = (const int*)d_in[1];
    float* out = (float*)d_out;

    const int T = 256;

    zero_deg_kernel<<<(NVERT + T - 1) / T, T>>>();
    count_deg_kernel<<<(NFACE + T - 1) / T, T>>>(faces);

    scan_reduce_kernel<<<NBLK, SCAN_B>>>();
    scan_spine_kernel<<<1, 256>>>();
    scan_final_kernel<<<NBLK, SCAN_B>>>();

    fill_adj_kernel<<<(NFACE + T - 1) / T, T>>>(faces);

    transpose_kernel<<<(NVERT + TVERTS - 1) / TVERTS, T>>>(vert);

    {
        int warps_per_block = T / 32;  // 8
        int blocks = (NVERT + warps_per_block - 1) / warps_per_block;
        gather_kernel<<<blocks, T>>>(out);
    }
}

// round 5
// speedup vs baseline: 4.2774x; 1.1061x over previous
#include <cuda_runtime.h>
#include <cstddef>

#define BATCH 16
#define NVERT 250000
#define NFACE 500000
#define NADJ  (6 * NFACE)          // 3,000,000 adjacency entries
#define SCAN_B 1024
#define NBLK ((NVERT + SCAN_B - 1) / SCAN_B)   // 245

// ---------------------------------------------------------------------------
// Device scratch (static; no runtime allocation allowed)
// ---------------------------------------------------------------------------
__device__ int    g_deg[NVERT];
__device__ int    g_start[NVERT];
__device__ int    g_cursor[NVERT];
__device__ int2   g_adj2[NADJ / 2];                 // pairs (all offsets even)
__device__ int    g_blocksum[NBLK];
__device__ int    g_blockoff[NBLK];
// [v][b][xyz] packed float3 rows: 48 floats = 192 B per vertex, 48 MB total
__device__ float  g_vert3[(size_t)NVERT * BATCH * 3];

// ---------------------------------------------------------------------------
// 1. Zero degrees
// ---------------------------------------------------------------------------
__global__ void zero_deg_kernel() {
    int i = blockIdx.x * blockDim.x + threadIdx.x;
    if (i < NVERT) g_deg[i] = 0;
}

// ---------------------------------------------------------------------------
// 2. Count degrees
// ---------------------------------------------------------------------------
__global__ void count_deg_kernel(const int* __restrict__ faces) {
    int f = blockIdx.x * blockDim.x + threadIdx.x;
    if (f >= NFACE) return;
    int a = faces[3 * f + 0];
    int b = faces[3 * f + 1];
    int c = faces[3 * f + 2];
    atomicAdd(&g_deg[a], 2);
    atomicAdd(&g_deg[b], 2);
    atomicAdd(&g_deg[c], 2);
}

// ---------------------------------------------------------------------------
// 3a. Per-block reduce of degrees (coalesced)
// ---------------------------------------------------------------------------
__global__ void scan_reduce_kernel() {
    __shared__ int sdata[SCAN_B / 32];
    int i = blockIdx.x * SCAN_B + threadIdx.x;
    int v = (i < NVERT) ? g_deg[i] : 0;
    for (int o = 16; o > 0; o >>= 1) v += __shfl_down_sync(0xffffffffu, v, o);
    if ((threadIdx.x & 31) == 0) sdata[threadIdx.x >> 5] = v;
    __syncthreads();
    if (threadIdx.x < 32) {
        int w = (threadIdx.x < SCAN_B / 32) ? sdata[threadIdx.x] : 0;
        for (int o = 16; o > 0; o >>= 1) w += __shfl_down_sync(0xffffffffu, w, o);
        if (threadIdx.x == 0) g_blocksum[blockIdx.x] = w;
    }
}

// ---------------------------------------------------------------------------
// 3b. Exclusive scan of block sums (parallel Hillis-Steele, one block)
// ---------------------------------------------------------------------------
__global__ void scan_spine_kernel() {
    __shared__ int s[256];
    int t = threadIdx.x;
    int v = (t < NBLK) ? g_blocksum[t] : 0;
    s[t] = v;
    __syncthreads();
    for (int d = 1; d < 256; d <<= 1) {
        int add = (t >= d) ? s[t - d] : 0;
        __syncthreads();
        s[t] += add;
        __syncthreads();
    }
    if (t < NBLK) g_blockoff[t] = s[t] - v;   // exclusive
}

// ---------------------------------------------------------------------------
// 3c. In-block exclusive scan + global offset (coalesced)
// ---------------------------------------------------------------------------
__global__ void scan_final_kernel() {
    __shared__ int s[SCAN_B];
    int t = threadIdx.x;
    int i = blockIdx.x * SCAN_B + t;
    int v = (i < NVERT) ? g_deg[i] : 0;
    s[t] = v;
    __syncthreads();
    for (int d = 1; d < SCAN_B; d <<= 1) {
        int add = (t >= d) ? s[t - d] : 0;
        __syncthreads();
        s[t] += add;
        __syncthreads();
    }
    if (i < NVERT) {
        int excl = s[t] - v + g_blockoff[blockIdx.x];
        g_start[i] = excl;
        g_cursor[i] = excl;
    }
}

// ---------------------------------------------------------------------------
// 4. Fill adjacency lists. Cursors are always even (degrees are even, scan of
//    evens is even), so each 2-entry append is one aligned int2 store.
// ---------------------------------------------------------------------------
__global__ void fill_adj_kernel(const int* __restrict__ faces) {
    int f = blockIdx.x * blockDim.x + threadIdx.x;
    if (f >= NFACE) return;
    int a = faces[3 * f + 0];
    int b = faces[3 * f + 1];
    int c = faces[3 * f + 2];

    int pa = atomicAdd(&g_cursor[a], 2);
    g_adj2[pa >> 1] = make_int2(b, c);
    int pb = atomicAdd(&g_cursor[b], 2);
    g_adj2[pb >> 1] = make_int2(a, c);
    int pc = atomicAdd(&g_cursor[c], 2);
    g_adj2[pc >> 1] = make_int2(a, b);
}

// ---------------------------------------------------------------------------
// 5. SMEM-tiled transpose: vert [B][N][3] -> g_vert3 [N][B][3]
//    Block handles 32 vertices: coalesced 384B row reads per batch,
//    fully coalesced contiguous 6KB write.
// ---------------------------------------------------------------------------
#define TVERTS 32
__global__ void __launch_bounds__(256)
transpose_kernel(const float* __restrict__ vert) {
    __shared__ float sm[BATCH][TVERTS * 3 + 1];   // +1 pad vs bank conflicts
    int v0 = blockIdx.x * TVERTS;
    int nv = NVERT - v0;
    if (nv > TVERTS) nv = TVERTS;
    int nfl = nv * 3;

    for (int i = threadIdx.x; i < BATCH * TVERTS * 3; i += 256) {
        int b = i / (TVERTS * 3);
        int r = i % (TVERTS * 3);
        if (r < nfl) {
            sm[b][r] = vert[((size_t)b * NVERT + v0) * 3 + r];
        }
    }
    __syncthreads();

    // Output region: g_vert3[v0*48 .. v0*48 + nv*48), contiguous
    float* dst = g_vert3 + (size_t)v0 * (BATCH * 3);
    for (int i = threadIdx.x; i < nv * BATCH * 3; i += 256) {
        int vv = i / (BATCH * 3);
        int r = i % (BATCH * 3);
        int b = r / 3;
        int c = r % 3;
        dst[i] = sm[b][vv * 3 + c];
    }
}

// ---------------------------------------------------------------------------
// 6. Gather + finalize: one warp per vertex.
//    lane l: batch b = l&15, parity j = l>>4; half-warp per neighbor row
//    (16 lanes x 12 B = 192 B contiguous per neighbor).
// ---------------------------------------------------------------------------
__global__ void __launch_bounds__(256)
gather_kernel(float* __restrict__ out) {
    int w = (blockIdx.x * blockDim.x + threadIdx.x) >> 5;
    if (w >= NVERT) return;
    int v = w;
    int lane = threadIdx.x & 31;
    int b = lane & 15;
    int j = lane >> 4;

    int s = g_start[v];
    int d = g_deg[v];

    float ax = 0.f, ay = 0.f, az = 0.f;
    const int* __restrict__ adj = reinterpret_cast<const int*>(g_adj2) + s;

    int k = j;
    int u = (k < d) ? __ldg(&adj[k]) : 0;
    while (k < d) {
        int k2 = k + 2;
        int u_next = (k2 < d) ? __ldg(&adj[k2]) : 0;   // prefetch: breaks chain
        const float* __restrict__ p = g_vert3 + ((size_t)u * (BATCH * 3) + b * 3);
        ax += __ldg(&p[0]);
        ay += __ldg(&p[1]);
        az += __ldg(&p[2]);
        u = u_next;
        k = k2;
    }

    ax += __shfl_xor_sync(0xffffffffu, ax, 16);
    ay += __shfl_xor_sync(0xffffffffu, ay, 16);
    az += __shfl_xor_sync(0xffffffffu, az, 16);

    if (j == 0) {
        float inv = 1.0f / fmaxf((float)d, 1.0f);
        const float* __restrict__ p = g_vert3 + ((size_t)v * (BATCH * 3) + b * 3);
        float lx = ax * inv - p[0];
        float ly = ay * inv - p[1];
        float lz = az * inv - p[2];
        out[(size_t)b * NVERT + v] = sqrtf(lx * lx + ly * ly + lz * lz);
    }
}

// ---------------------------------------------------------------------------
extern "C" void kernel_launch(void* const* d_in, const int* in_sizes, int n_in,
                              void* d_out, int out_size) {
    const float* vert = (const float*)d_in[0];
    const int* faces = (const int*)d_in[1];
    float* out = (float*)d_out;

    const int T = 256;

    zero_deg_kernel<<<(NVERT + T - 1) / T, T>>>();
    count_deg_kernel<<<(NFACE + T - 1) / T, T>>>(faces);

    scan_reduce_kernel<<<NBLK, SCAN_B>>>();
    scan_spine_kernel<<<1, 256>>>();
    scan_final_kernel<<<NBLK, SCAN_B>>>();

    fill_adj_kernel<<<(NFACE + T - 1) / T, T>>>(faces);

    transpose_kernel<<<(NVERT + TVERTS - 1) / TVERTS, T>>>(vert);

    {
        int warps_per_block = T / 32;  // 8
        int blocks = (NVERT + warps_per_block - 1) / warps_per_block;
        gather_kernel<<<blocks, T>>>(out);
    }
}